// round 7
// baseline (speedup 1.0000x reference)
#include <cuda_runtime.h>
#include <math.h>

#define NT 192
#define BB 256
#define TT 512
#define DT_F 0.01

struct Smem {
    // ---- fp64 state & scratch (first for alignment) ----
    double Qd[12][12]; double Rd[9][9];
    double x[12]; double P[12][12];
    double xp[12]; double u[4]; double z[9];
    double a0d[64]; double a1d[64]; double a2d[32];
    double M[12][12]; double Pp[12][12];
    double PHt[12][9]; double Saug[9][22];   // [S(9) | PHt^T(12) | pad]
    double K[12][9]; double KH[12][12];
    double zp[9]; double innov[9]; double xn[12];
    // ---- weights (fp32, resident whole kernel) ----
    float dW0[16][64]; float db0[64];
    float dW1[64][64]; float db1[64];
    float dW2[64][32]; float db2[32];
    float dW3[32][12]; float db3[12];
    float mW0[12][64]; float mb0[64];
    float mW1[64][64]; float mb1[64];
    float mW2[64][9];  float mb2[9];
    // ---- fp32 Jacobian-chain scratch (noise-suppressed path) ----
    float a0f[64]; float a1f[64]; float a2f[32];
    float D0[12][64]; float D1[12][64]; float D2[12][33]; // pad 33
    float F[12][12]; float H[9][12];
};

__global__ void __launch_bounds__(NT, 1) ekf_kernel(
    const float* __restrict__ g_ctl,  const float* __restrict__ g_meas,
    const float* __restrict__ g_x0,   const float* __restrict__ g_P0,
    const float* __restrict__ g_Q,    const float* __restrict__ g_R,
    const float* __restrict__ g_dW0, const float* __restrict__ g_db0,
    const float* __restrict__ g_dW1, const float* __restrict__ g_db1,
    const float* __restrict__ g_dW2, const float* __restrict__ g_db2,
    const float* __restrict__ g_dW3, const float* __restrict__ g_db3,
    const float* __restrict__ g_mW0, const float* __restrict__ g_mb0,
    const float* __restrict__ g_mW1, const float* __restrict__ g_mb1,
    const float* __restrict__ g_mW2, const float* __restrict__ g_mb2,
    float* __restrict__ o_est, float* __restrict__ o_zp, float* __restrict__ o_cov)
{
    extern __shared__ char raw[];
    Smem& s = *reinterpret_cast<Smem*>(raw);
    const int tid = threadIdx.x;
    const int b = blockIdx.x;

    // ---- stage weights & per-batch initial state ----
    {
        float* d;
        d=&s.dW0[0][0]; for (int i=tid;i<16*64;i+=NT) d[i]=g_dW0[i];
        for (int i=tid;i<64;i+=NT) s.db0[i]=g_db0[i];
        d=&s.dW1[0][0]; for (int i=tid;i<64*64;i+=NT) d[i]=g_dW1[i];
        for (int i=tid;i<64;i+=NT) s.db1[i]=g_db1[i];
        d=&s.dW2[0][0]; for (int i=tid;i<64*32;i+=NT) d[i]=g_dW2[i];
        for (int i=tid;i<32;i+=NT) s.db2[i]=g_db2[i];
        d=&s.dW3[0][0]; for (int i=tid;i<32*12;i+=NT) d[i]=g_dW3[i];
        if (tid<12) s.db3[tid]=g_db3[tid];
        d=&s.mW0[0][0]; for (int i=tid;i<12*64;i+=NT) d[i]=g_mW0[i];
        for (int i=tid;i<64;i+=NT) s.mb0[i]=g_mb0[i];
        d=&s.mW1[0][0]; for (int i=tid;i<64*64;i+=NT) d[i]=g_mW1[i];
        for (int i=tid;i<64;i+=NT) s.mb1[i]=g_mb1[i];
        d=&s.mW2[0][0]; for (int i=tid;i<64*9;i+=NT) d[i]=g_mW2[i];
        if (tid<9) s.mb2[tid]=g_mb2[tid];
        {
            double* q=&s.Qd[0][0]; for (int i=tid;i<144;i+=NT) q[i]=(double)g_Q[i];
            double* r=&s.Rd[0][0]; for (int i=tid;i<81;i+=NT)  r[i]=(double)g_R[i];
            if (tid<12) s.x[tid]=(double)g_x0[b*12+tid];
            double* p=&s.P[0][0]; for (int i=tid;i<144;i+=NT) p[i]=(double)g_P0[b*144+i];
        }
    }
    __syncthreads();

    const int jj  = tid & 63;   // column 0..63
    const int ib3 = tid >> 6;   // 0..2   (rows i = ib3 + 3r, r<4)
    const int j32 = tid & 31;
    const int ib6 = tid >> 5;   // 0..5   (rows i = ib6 + 6r, r<2)

    #pragma unroll 1
    for (int t = 0; t < TT; ++t) {
        if (tid < 4) s.u[tid] = (double)g_ctl [((long)b*TT + t)*4 + tid];
        if (tid < 9) s.z[tid] = (double)g_meas[((long)b*TT + t)*9 + tid];
        __syncthreads();

        if (t > 0) {
            // ===== PREDICT =====
            // dyn layer0: a0 = tanh([x,u] @ dW0 + db0)   (fp64 forward)
            if (tid < 64) {
                double acc = (double)s.db0[tid];
                #pragma unroll
                for (int i=0;i<12;i++) acc = fma(s.x[i], (double)s.dW0[i][tid], acc);
                #pragma unroll
                for (int i=0;i<4;i++)  acc = fma(s.u[i], (double)s.dW0[12+i][tid], acc);
                double a = tanh(acc);
                s.a0d[tid] = a; s.a0f[tid] = (float)a;
            }
            __syncthreads();
            // D0 (fp32 chain) ; a1 fp64
            {
                float av = s.a0f[jj];
                float g = 1.f - av*av;
                #pragma unroll
                for (int r=0;r<4;r++) s.D0[ib3+3*r][jj] = s.dW0[ib3+3*r][jj]*g;
            }
            if (tid < 64) {
                double acc = (double)s.db1[tid];
                #pragma unroll 8
                for (int k=0;k<64;k++) acc = fma(s.a0d[k], (double)s.dW1[k][tid], acc);
                double a = tanh(acc);
                s.a1d[tid] = a; s.a1f[tid] = (float)a;
            }
            __syncthreads();
            // D1 = (D0 @ dW1)*(1-a1^2) fp32 ; a2 fp64
            {
                float c0=0,c1=0,c2=0,c3=0;
                #pragma unroll 4
                for (int k=0;k<64;k++) {
                    float w = s.dW1[k][jj];
                    c0 = fmaf(s.D0[ib3+0][k], w, c0);
                    c1 = fmaf(s.D0[ib3+3][k], w, c1);
                    c2 = fmaf(s.D0[ib3+6][k], w, c2);
                    c3 = fmaf(s.D0[ib3+9][k], w, c3);
                }
                float av = s.a1f[jj];
                float g = 1.f - av*av;
                s.D1[ib3+0][jj]=c0*g; s.D1[ib3+3][jj]=c1*g;
                s.D1[ib3+6][jj]=c2*g; s.D1[ib3+9][jj]=c3*g;
            }
            if (tid < 32) {
                double acc = (double)s.db2[tid];
                #pragma unroll 8
                for (int k=0;k<64;k++) acc = fma(s.a1d[k], (double)s.dW2[k][tid], acc);
                double a = tanh(acc);
                s.a2d[tid] = a; s.a2f[tid] = (float)a;
            }
            __syncthreads();
            // D2 fp32 ; residual + xp fp64
            {
                float c0=0,c1=0;
                #pragma unroll 4
                for (int k=0;k<64;k++) {
                    float w = s.dW2[k][j32];
                    c0 = fmaf(s.D1[ib6+0][k], w, c0);
                    c1 = fmaf(s.D1[ib6+6][k], w, c1);
                }
                float av = s.a2f[j32];
                float g = 1.f - av*av;
                s.D2[ib6+0][j32]=c0*g; s.D2[ib6+6][j32]=c1*g;
            }
            if (tid < 12) {
                double acc = (double)s.db3[tid];
                #pragma unroll 8
                for (int k=0;k<32;k++) acc = fma(s.a2d[k], (double)s.dW3[k][tid], acc);
                double drift = 0.0;
                if (tid < 3)                  drift = s.x[tid+3];
                else if (tid >= 6 && tid < 9) drift = s.x[tid+3];
                s.xp[tid] = s.x[tid] + DT_F*drift + acc;
            }
            __syncthreads();
            // F fp32 (chain tail)
            if (tid < 144) {
                int a = tid/12, i = tid - a*12;
                float acc = (a==i) ? 1.f : 0.f;
                if ((a<3 || (a>=6 && a<9)) && i == a+3) acc += 0.01f;
                #pragma unroll 8
                for (int k=0;k<32;k++) acc = fmaf(s.D2[i][k], s.dW3[k][a], acc);
                s.F[a][i] = acc;
            }
            __syncthreads();
            // M = F @ P   (fp64)
            if (tid < 144) {
                int a = tid/12, j = tid - a*12;
                double acc = 0.0;
                #pragma unroll
                for (int i=0;i<12;i++) acc = fma((double)s.F[a][i], s.P[i][j], acc);
                s.M[a][j] = acc;
            }
            __syncthreads();
            // Pp = M @ F^T + Q  (fp64)
            if (tid < 144) {
                int a = tid/12, c = tid - a*12;
                double acc = s.Qd[a][c];
                #pragma unroll
                for (int j=0;j<12;j++) acc = fma(s.M[a][j], (double)s.F[c][j], acc);
                s.Pp[a][c] = acc;
            }
            __syncthreads();
        } else {
            if (tid < 12) s.xp[tid] = s.x[tid];
            if (tid < 144) { int a=tid/12, j=tid-a*12; s.Pp[a][j] = s.P[a][j]; }
            __syncthreads();
        }

        // ===== UPDATE =====
        // meas layer0 fp64
        if (tid < 64) {
            double acc = (double)s.mb0[tid];
            #pragma unroll
            for (int i=0;i<12;i++) acc = fma(s.xp[i], (double)s.mW0[i][tid], acc);
            double a = (acc > 0.0) ? acc : 0.0;
            s.a0d[tid] = a; s.a0f[tid] = (float)a;
        }
        __syncthreads();
        // Dm0 fp32 ; layer1 fp64
        {
            float g = (s.a0f[jj] > 0.f) ? 1.f : 0.f;
            #pragma unroll
            for (int r=0;r<4;r++) s.D0[ib3+3*r][jj] = s.mW0[ib3+3*r][jj]*g;
        }
        if (tid < 64) {
            double acc = (double)s.mb1[tid];
            #pragma unroll 8
            for (int k=0;k<64;k++) acc = fma(s.a0d[k], (double)s.mW1[k][tid], acc);
            double a = (acc > 0.0) ? acc : 0.0;
            s.a1d[tid] = a; s.a1f[tid] = (float)a;
        }
        __syncthreads();
        // Dm1 fp32 ; z_pred + innovation fp64
        {
            float c0=0,c1=0,c2=0,c3=0;
            #pragma unroll 4
            for (int k=0;k<64;k++) {
                float w = s.mW1[k][jj];
                c0 = fmaf(s.D0[ib3+0][k], w, c0);
                c1 = fmaf(s.D0[ib3+3][k], w, c1);
                c2 = fmaf(s.D0[ib3+6][k], w, c2);
                c3 = fmaf(s.D0[ib3+9][k], w, c3);
            }
            float g = (s.a1f[jj] > 0.f) ? 1.f : 0.f;
            s.D1[ib3+0][jj]=c0*g; s.D1[ib3+3][jj]=c1*g;
            s.D1[ib3+6][jj]=c2*g; s.D1[ib3+9][jj]=c3*g;
        }
        if (tid < 9) {
            double acc = (double)s.mb2[tid];
            #pragma unroll 8
            for (int k=0;k<64;k++) acc = fma(s.a1d[k], (double)s.mW2[k][tid], acc);
            double zpv = s.xp[tid] + acc;
            s.zp[tid]    = zpv;
            s.innov[tid] = s.z[tid] - zpv;
        }
        __syncthreads();
        // H fp32 (chain tail)
        if (tid < 108) {
            int a = tid/12, i = tid - a*12;
            float acc = (a==i) ? 1.f : 0.f;
            #pragma unroll 8
            for (int k=0;k<64;k++) acc = fmaf(s.D1[i][k], s.mW2[k][a], acc);
            s.H[a][i] = acc;
        }
        __syncthreads();
        // PHt = Pp @ H^T  (fp64)
        if (tid < 108) {
            int i = tid/9, a = tid - i*9;
            double acc = 0.0;
            #pragma unroll
            for (int j=0;j<12;j++) acc = fma(s.Pp[i][j], (double)s.H[a][j], acc);
            s.PHt[i][a] = acc;
        }
        __syncthreads();
        // Augmented [S | PHt^T]  (fp64)
        if (tid < 81) {
            int a = tid/9, c = tid - a*9;
            double acc = s.Rd[a][c];
            #pragma unroll
            for (int i=0;i<12;i++) acc = fma((double)s.H[a][i], s.PHt[i][c], acc);
            s.Saug[a][c] = acc;
        } else if (tid < 81 + 108) {
            int e = tid - 81;
            int a = e/12, i = e - a*12;
            s.Saug[a][9+i] = s.PHt[i][a];
        }
        __syncthreads();
        // Unpivoted Gauss-Jordan on SPD S (fp64). Writes only cols > k.
        #pragma unroll 1
        for (int k=0;k<9;k++) {
            const int nc = 20 - k;
            const double inv = 1.0 / s.Saug[k][k];
            for (int e = tid; e < 8*nc; e += NT) {
                int i = e / nc; i += (i >= k);
                int c = k + 1 + (e - (e/nc)*nc);
                s.Saug[i][c] -= s.Saug[i][k] * inv * s.Saug[k][c];
            }
            __syncthreads();
        }
        if (tid < 108) {
            int i = tid/9, a = tid - i*9;
            s.K[i][a] = s.Saug[a][9+i] / s.Saug[a][a];
        }
        __syncthreads();
        // x_new ; KH  (fp64)
        if (tid < 12) {
            double acc = s.xp[tid];
            #pragma unroll
            for (int a=0;a<9;a++) acc = fma(s.K[tid][a], s.innov[a], acc);
            s.xn[tid] = acc;
        }
        if (tid < 144) {
            int i = tid/12, j = tid - i*12;
            double acc = 0.0;
            #pragma unroll
            for (int a=0;a<9;a++) acc = fma(s.K[i][a], (double)s.H[a][j], acc);
            s.KH[i][j] = acc;
        }
        __syncthreads();
        // P_new = Pp - KH @ Pp ; commit x  (fp64)
        if (tid < 144) {
            int i = tid/12, j = tid - i*12;
            double acc = s.Pp[i][j];
            #pragma unroll
            for (int k=0;k<12;k++) acc = fma(-s.KH[i][k], s.Pp[k][j], acc);
            s.P[i][j] = acc;
        }
        if (tid < 12) s.x[tid] = s.xn[tid];
        __syncthreads();

        // ===== STORE (fp32 outputs) =====
        {
            long base = (long)b*TT + t;
            if (tid < 12)  o_est[base*12 + tid] = (float)s.x[tid];
            if (tid < 9)   o_zp [base*9  + tid] = (float)s.zp[tid];
            if (tid < 144) o_cov[base*144 + tid] = (float)(&s.P[0][0])[tid];
        }
        // next-iteration u/z load + barrier orders scratch reuse
    }
}

extern "C" void kernel_launch(void* const* d_in, const int* in_sizes, int n_in,
                              void* d_out, int out_size)
{
    const float* ctl  = (const float*)d_in[1];
    const float* meas = (const float*)d_in[2];
    const float* x0   = (const float*)d_in[3];
    const float* P0   = (const float*)d_in[4];
    const float* Q    = (const float*)d_in[5];
    const float* R    = (const float*)d_in[6];
    const float* dW0  = (const float*)d_in[7];  const float* db0 = (const float*)d_in[8];
    const float* dW1  = (const float*)d_in[9];  const float* db1 = (const float*)d_in[10];
    const float* dW2  = (const float*)d_in[11]; const float* db2 = (const float*)d_in[12];
    const float* dW3  = (const float*)d_in[13]; const float* db3 = (const float*)d_in[14];
    const float* mW0  = (const float*)d_in[15]; const float* mb0 = (const float*)d_in[16];
    const float* mW1  = (const float*)d_in[17]; const float* mb1 = (const float*)d_in[18];
    const float* mW2  = (const float*)d_in[19]; const float* mb2 = (const float*)d_in[20];

    float* out   = (float*)d_out;
    float* o_est = out;                        // [B,T,12]
    float* o_zp  = out + (long)BB*TT*12;       // [B,T,9]
    float* o_cov = out + (long)BB*TT*(12+9);   // [B,T,12,12]

    int smem = (int)sizeof(Smem);
    cudaFuncSetAttribute(ekf_kernel, cudaFuncAttributeMaxDynamicSharedMemorySize, smem);
    ekf_kernel<<<BB, NT, smem>>>(ctl, meas, x0, P0, Q, R,
        dW0,db0,dW1,db1,dW2,db2,dW3,db3,
        mW0,mb0,mW1,mb1,mW2,mb2,
        o_est, o_zp, o_cov);
}

// round 10
// speedup vs baseline: 1.5503x; 1.5503x over previous
#include <cuda_runtime.h>
#include <math.h>

#define NT 192
#define BB 256
#define TT 512

struct Smem {
    // ---- fp64 state & scratch ----
    double Qd[12][12]; double Rd[9][9];
    double x[12]; double P[12][12];
    double xp[12];
    double M[12][12]; double Pp[12][12];
    double PHt[12][9]; double Saug[9][22];   // [S(9) | PHt^T(12) | pad]
    double K[12][9]; double KH[12][12];
    double zp[9]; double innov[9]; double xn[12];
    double rdiag[9];
    // ---- fp32: split state, inputs, activations ----
    float xh[12]; float xl[12]; float xph[12]; float xpl[12];
    float uf[4]; float zf[9];
    float a0h[64]; float a0l[64];
    float a1h[64]; float a1l[64];
    float a2h[32]; float a2l[32];
    // ---- weights (fp32, resident) ----
    float dW0[16][64]; float db0[64];
    float dW1[64][64]; float db1[64];
    float dW2[64][32]; float db2[32];
    float dW3[32][12]; float db3[12];
    float mW0[12][64]; float mb0[64];
    float mW1[64][64]; float mb1[64];
    float mW2[64][9];  float mb2[9];
    // ---- fp32 Jacobian-chain scratch ----
    float D0[12][64]; float D1[12][64]; float D2[12][33]; // pad 33
    float F[12][12]; float H[9][12];
};

// TwoSum-based compensated accumulation: (s,c) += p + e, exact on (s,p).
__device__ __forceinline__ void d2acc(float &s, float &c, float p, float e) {
    float t  = s + p;
    float bb = t - s;
    float err = (s - (t - bb)) + (p - bb);
    s = t;
    c += err + e;
}
// accumulate (ah+al)*w into (s,c) with exact product splitting
__device__ __forceinline__ void dotp(float &s, float &c, float ah, float al, float w) {
    float p = ah * w;
    float e = fmaf(ah, w, -p);   // exact tail of ah*w
    e = fmaf(al, w, e);
    d2acc(s, c, p, e);
}
__device__ __forceinline__ double dmerge(float s1, float c1, float s2, float c2) {
    return ((double)s1 + (double)s2) + ((double)c1 + (double)c2);
}
__device__ __forceinline__ void dsplit(double a, float &h, float &l) {
    float hf = (float)a;
    h = hf; l = (float)(a - (double)hf);
}
// float-seeded Newton reciprocal: exact to ~1 ulp fp64, no DDIV
__device__ __forceinline__ double fastrcp(double v) {
    double r = (double)__frcp_rn((float)v);
    r = r * fma(-v, r, 2.0);
    r = r * fma(-v, r, 2.0);
    return r;
}

__global__ void __launch_bounds__(NT, 1) ekf_kernel(
    const float* __restrict__ g_ctl,  const float* __restrict__ g_meas,
    const float* __restrict__ g_x0,   const float* __restrict__ g_P0,
    const float* __restrict__ g_Q,    const float* __restrict__ g_R,
    const float* __restrict__ g_dW0, const float* __restrict__ g_db0,
    const float* __restrict__ g_dW1, const float* __restrict__ g_db1,
    const float* __restrict__ g_dW2, const float* __restrict__ g_db2,
    const float* __restrict__ g_dW3, const float* __restrict__ g_db3,
    const float* __restrict__ g_mW0, const float* __restrict__ g_mb0,
    const float* __restrict__ g_mW1, const float* __restrict__ g_mb1,
    const float* __restrict__ g_mW2, const float* __restrict__ g_mb2,
    float* __restrict__ o_est, float* __restrict__ o_zp, float* __restrict__ o_cov)
{
    extern __shared__ char raw[];
    Smem& s = *reinterpret_cast<Smem*>(raw);
    const int tid = threadIdx.x;
    const int b = blockIdx.x;

    // ---- stage weights & per-batch initial state ----
    {
        float* d;
        d=&s.dW0[0][0]; for (int i=tid;i<16*64;i+=NT) d[i]=g_dW0[i];
        for (int i=tid;i<64;i+=NT) s.db0[i]=g_db0[i];
        d=&s.dW1[0][0]; for (int i=tid;i<64*64;i+=NT) d[i]=g_dW1[i];
        for (int i=tid;i<64;i+=NT) s.db1[i]=g_db1[i];
        d=&s.dW2[0][0]; for (int i=tid;i<64*32;i+=NT) d[i]=g_dW2[i];
        for (int i=tid;i<32;i+=NT) s.db2[i]=g_db2[i];
        d=&s.dW3[0][0]; for (int i=tid;i<32*12;i+=NT) d[i]=g_dW3[i];
        if (tid<12) s.db3[tid]=g_db3[tid];
        d=&s.mW0[0][0]; for (int i=tid;i<12*64;i+=NT) d[i]=g_mW0[i];
        for (int i=tid;i<64;i+=NT) s.mb0[i]=g_mb0[i];
        d=&s.mW1[0][0]; for (int i=tid;i<64*64;i+=NT) d[i]=g_mW1[i];
        for (int i=tid;i<64;i+=NT) s.mb1[i]=g_mb1[i];
        d=&s.mW2[0][0]; for (int i=tid;i<64*9;i+=NT) d[i]=g_mW2[i];
        if (tid<9) s.mb2[tid]=g_mb2[tid];
        double* q=&s.Qd[0][0]; for (int i=tid;i<144;i+=NT) q[i]=(double)g_Q[i];
        double* r=&s.Rd[0][0]; for (int i=tid;i<81;i+=NT)  r[i]=(double)g_R[i];
        if (tid<12) {
            double xv = (double)g_x0[b*12+tid];
            s.x[tid]=xv; dsplit(xv, s.xh[tid], s.xl[tid]);
        }
        double* p=&s.P[0][0]; for (int i=tid;i<144;i+=NT) p[i]=(double)g_P0[b*144+i];
    }
    __syncthreads();

    const int jj  = tid & 63;   // column 0..63
    const int ib3 = tid >> 6;   // 0..2   (rows i = ib3 + 3r, r<4)
    const int j32 = tid & 31;
    const int ib6 = tid >> 5;   // 0..5   (rows i = ib6 + 6r, r<2)

    #pragma unroll 1
    for (int t = 0; t < TT; ++t) {
        if (tid < 4) s.uf[tid] = g_ctl [((long)b*TT + t)*4 + tid];
        if (tid < 9) s.zf[tid] = g_meas[((long)b*TT + t)*9 + tid];
        __syncthreads();

        if (t > 0) {
            // ===== PREDICT =====
            // L0: a0 = tanh([x,u] @ dW0 + db0)  (dot2 fp32 -> double tanh)
            if (tid < 64) {
                float s1 = s.db0[tid], c1 = 0.f;
                #pragma unroll
                for (int i=0;i<12;i++) dotp(s1,c1, s.xh[i], s.xl[i], s.dW0[i][tid]);
                #pragma unroll
                for (int i=0;i<4;i++) {
                    float w = s.dW0[12+i][tid];
                    float p = s.uf[i]*w;
                    float e = fmaf(s.uf[i], w, -p);
                    d2acc(s1,c1,p,e);
                }
                double a = tanh((double)s1 + (double)c1);
                dsplit(a, s.a0h[tid], s.a0l[tid]);
            }
            __syncthreads();
            // D0 (fp32 chain); L1 (dot2)
            {
                float av = s.a0h[jj];
                float g = 1.f - av*av;
                #pragma unroll
                for (int r=0;r<4;r++) s.D0[ib3+3*r][jj] = s.dW0[ib3+3*r][jj]*g;
            }
            if (tid < 64) {
                float s1=s.db1[tid], c1=0.f, s2=0.f, c2=0.f;
                #pragma unroll 8
                for (int k=0;k<64;k+=2) {
                    dotp(s1,c1, s.a0h[k],   s.a0l[k],   s.dW1[k][tid]);
                    dotp(s2,c2, s.a0h[k+1], s.a0l[k+1], s.dW1[k+1][tid]);
                }
                double a = tanh(dmerge(s1,c1,s2,c2));
                dsplit(a, s.a1h[tid], s.a1l[tid]);
            }
            __syncthreads();
            // D1 = (D0 @ dW1)*(1-a1^2) fp32 ; L2 dot2
            {
                float c0=0,c1=0,c2=0,c3=0;
                #pragma unroll 4
                for (int k=0;k<64;k++) {
                    float w = s.dW1[k][jj];
                    c0 = fmaf(s.D0[ib3+0][k], w, c0);
                    c1 = fmaf(s.D0[ib3+3][k], w, c1);
                    c2 = fmaf(s.D0[ib3+6][k], w, c2);
                    c3 = fmaf(s.D0[ib3+9][k], w, c3);
                }
                float av = s.a1h[jj];
                float g = 1.f - av*av;
                s.D1[ib3+0][jj]=c0*g; s.D1[ib3+3][jj]=c1*g;
                s.D1[ib3+6][jj]=c2*g; s.D1[ib3+9][jj]=c3*g;
            }
            if (tid < 32) {
                float s1=s.db2[tid], c1=0.f, s2=0.f, c2=0.f;
                #pragma unroll 8
                for (int k=0;k<64;k+=2) {
                    dotp(s1,c1, s.a1h[k],   s.a1l[k],   s.dW2[k][tid]);
                    dotp(s2,c2, s.a1h[k+1], s.a1l[k+1], s.dW2[k+1][tid]);
                }
                double a = tanh(dmerge(s1,c1,s2,c2));
                dsplit(a, s.a2h[tid], s.a2l[tid]);
            }
            __syncthreads();
            // D2 fp32 ; residual + xp
            {
                float c0=0,c1=0;
                #pragma unroll 4
                for (int k=0;k<64;k++) {
                    float w = s.dW2[k][j32];
                    c0 = fmaf(s.D1[ib6+0][k], w, c0);
                    c1 = fmaf(s.D1[ib6+6][k], w, c1);
                }
                float av = s.a2h[j32];
                float g = 1.f - av*av;
                s.D2[ib6+0][j32]=c0*g; s.D2[ib6+6][j32]=c1*g;
            }
            if (tid < 12) {
                float s1=s.db3[tid], c1=0.f, s2=0.f, c2=0.f;
                #pragma unroll 8
                for (int k=0;k<32;k+=2) {
                    dotp(s1,c1, s.a2h[k],   s.a2l[k],   s.dW3[k][tid]);
                    dotp(s2,c2, s.a2h[k+1], s.a2l[k+1], s.dW3[k+1][tid]);
                }
                double resid = dmerge(s1,c1,s2,c2);
                double drift = 0.0;
                if (tid < 3)                  drift = s.x[tid+3];
                else if (tid >= 6 && tid < 9) drift = s.x[tid+3];
                double xpv = s.x[tid] + 0.01*drift + resid;
                s.xp[tid] = xpv;
                dsplit(xpv, s.xph[tid], s.xpl[tid]);
            }
            __syncthreads();
            // F fp32
            if (tid < 144) {
                int a = tid/12, i = tid - a*12;
                float acc = (a==i) ? 1.f : 0.f;
                if ((a<3 || (a>=6 && a<9)) && i == a+3) acc += 0.01f;
                #pragma unroll 8
                for (int k=0;k<32;k++) acc = fmaf(s.D2[i][k], s.dW3[k][a], acc);
                s.F[a][i] = acc;
            }
            __syncthreads();
            // M = F @ P  (fp64)
            if (tid < 144) {
                int a = tid/12, j = tid - a*12;
                double acc = 0.0;
                #pragma unroll
                for (int i=0;i<12;i++) acc = fma((double)s.F[a][i], s.P[i][j], acc);
                s.M[a][j] = acc;
            }
            __syncthreads();
            // Pp = M @ F^T + Q  (fp64)
            if (tid < 144) {
                int a = tid/12, c = tid - a*12;
                double acc = s.Qd[a][c];
                #pragma unroll
                for (int j=0;j<12;j++) acc = fma(s.M[a][j], (double)s.F[c][j], acc);
                s.Pp[a][c] = acc;
            }
            __syncthreads();
        } else {
            if (tid < 12) {
                s.xp[tid] = s.x[tid];
                s.xph[tid] = s.xh[tid]; s.xpl[tid] = s.xl[tid];
            }
            if (tid < 144) { int a=tid/12, j=tid-a*12; s.Pp[a][j] = s.P[a][j]; }
            __syncthreads();
        }

        // ===== UPDATE =====
        // mL0: relu(xp @ mW0 + mb0)  (dot2)
        if (tid < 64) {
            float s1 = s.mb0[tid], c1 = 0.f;
            #pragma unroll
            for (int i=0;i<12;i++) dotp(s1,c1, s.xph[i], s.xpl[i], s.mW0[i][tid]);
            double a = (double)s1 + (double)c1;
            if (a < 0.0) a = 0.0;
            dsplit(a, s.a0h[tid], s.a0l[tid]);
        }
        __syncthreads();
        // Dm0 fp32 ; mL1 dot2
        {
            float g = (s.a0h[jj] > 0.f) ? 1.f : 0.f;
            #pragma unroll
            for (int r=0;r<4;r++) s.D0[ib3+3*r][jj] = s.mW0[ib3+3*r][jj]*g;
        }
        if (tid < 64) {
            float s1=s.mb1[tid], c1=0.f, s2=0.f, c2=0.f;
            #pragma unroll 8
            for (int k=0;k<64;k+=2) {
                dotp(s1,c1, s.a0h[k],   s.a0l[k],   s.mW1[k][tid]);
                dotp(s2,c2, s.a0h[k+1], s.a0l[k+1], s.mW1[k+1][tid]);
            }
            double a = dmerge(s1,c1,s2,c2);
            if (a < 0.0) a = 0.0;
            dsplit(a, s.a1h[tid], s.a1l[tid]);
        }
        __syncthreads();
        // Dm1 fp32 ; z_pred + innovation
        {
            float c0=0,c1=0,c2=0,c3=0;
            #pragma unroll 4
            for (int k=0;k<64;k++) {
                float w = s.mW1[k][jj];
                c0 = fmaf(s.D0[ib3+0][k], w, c0);
                c1 = fmaf(s.D0[ib3+3][k], w, c1);
                c2 = fmaf(s.D0[ib3+6][k], w, c2);
                c3 = fmaf(s.D0[ib3+9][k], w, c3);
            }
            float g = (s.a1h[jj] > 0.f) ? 1.f : 0.f;
            s.D1[ib3+0][jj]=c0*g; s.D1[ib3+3][jj]=c1*g;
            s.D1[ib3+6][jj]=c2*g; s.D1[ib3+9][jj]=c3*g;
        }
        if (tid < 9) {
            float s1=s.mb2[tid], c1=0.f, s2=0.f, c2=0.f;
            #pragma unroll 8
            for (int k=0;k<64;k+=2) {
                dotp(s1,c1, s.a1h[k],   s.a1l[k],   s.mW2[k][tid]);
                dotp(s2,c2, s.a1h[k+1], s.a1l[k+1], s.mW2[k+1][tid]);
            }
            double zpv = s.xp[tid] + dmerge(s1,c1,s2,c2);
            s.zp[tid]    = zpv;
            s.innov[tid] = (double)s.zf[tid] - zpv;
        }
        __syncthreads();
        // H fp32
        if (tid < 108) {
            int a = tid/12, i = tid - a*12;
            float acc = (a==i) ? 1.f : 0.f;
            #pragma unroll 8
            for (int k=0;k<64;k++) acc = fmaf(s.D1[i][k], s.mW2[k][a], acc);
            s.H[a][i] = acc;
        }
        __syncthreads();
        // PHt = Pp @ H^T  (fp64)
        if (tid < 108) {
            int i = tid/9, a = tid - i*9;
            double acc = 0.0;
            #pragma unroll
            for (int j=0;j<12;j++) acc = fma(s.Pp[i][j], (double)s.H[a][j], acc);
            s.PHt[i][a] = acc;
        }
        __syncthreads();
        // Augmented [S | PHt^T]  (fp64); thread (0,0) seeds rdiag[0]
        if (tid < 81) {
            int a = tid/9, c = tid - a*9;
            double acc = s.Rd[a][c];
            #pragma unroll
            for (int i=0;i<12;i++) acc = fma((double)s.H[a][i], s.PHt[i][c], acc);
            s.Saug[a][c] = acc;
            if (tid == 0) s.rdiag[0] = fastrcp(acc);   // (0,0) never touched again
        } else if (tid < 81 + 108) {
            int e = tid - 81;
            int a = e/12, i = e - a*12;
            s.Saug[a][9+i] = s.PHt[i][a];
        }
        __syncthreads();
        // Unpivoted Gauss-Jordan on SPD S (fp64), reciprocal from smem (no DDIV).
        // The thread finalizing diag (k+1,k+1) also produces rdiag[k+1].
        #pragma unroll 1
        for (int k=0;k<9;k++) {
            const int nc = 20 - k;
            const double inv = s.rdiag[k];
            for (int e = tid; e < 8*nc; e += NT) {
                int i = e / nc; i += (i >= k);
                int c = k + 1 + (e - (e/nc)*nc);
                double v = s.Saug[i][c] - s.Saug[i][k] * inv * s.Saug[k][c];
                s.Saug[i][c] = v;
                if (i == k+1 && c == k+1) s.rdiag[k+1] = fastrcp(v);
            }
            __syncthreads();
        }
        // K[i][a] = Saug[a][9+i] * rdiag[a]   (no division)
        if (tid < 108) {
            int i = tid/9, a = tid - i*9;
            s.K[i][a] = s.Saug[a][9+i] * s.rdiag[a];
        }
        __syncthreads();
        // x_new ; KH  (fp64)
        if (tid < 12) {
            double acc = s.xp[tid];
            #pragma unroll
            for (int a=0;a<9;a++) acc = fma(s.K[tid][a], s.innov[a], acc);
            s.xn[tid] = acc;
        }
        if (tid < 144) {
            int i = tid/12, j = tid - i*12;
            double acc = 0.0;
            #pragma unroll
            for (int a=0;a<9;a++) acc = fma(s.K[i][a], (double)s.H[a][j], acc);
            s.KH[i][j] = acc;
        }
        __syncthreads();
        // P_new = Pp - KH @ Pp ; commit x (+ split)
        if (tid < 144) {
            int i = tid/12, j = tid - i*12;
            double acc = s.Pp[i][j];
            #pragma unroll
            for (int k=0;k<12;k++) acc = fma(-s.KH[i][k], s.Pp[k][j], acc);
            s.P[i][j] = acc;
        }
        if (tid < 12) {
            double xv = s.xn[tid];
            s.x[tid] = xv;
            dsplit(xv, s.xh[tid], s.xl[tid]);
        }
        __syncthreads();

        // ===== STORE (fp32 outputs) =====
        {
            long base = (long)b*TT + t;
            if (tid < 12)  o_est[base*12 + tid] = (float)s.x[tid];
            if (tid < 9)   o_zp [base*9  + tid] = (float)s.zp[tid];
            if (tid < 144) o_cov[base*144 + tid] = (float)(&s.P[0][0])[tid];
        }
        // next-iteration u/z load + barrier orders scratch reuse
    }
}

extern "C" void kernel_launch(void* const* d_in, const int* in_sizes, int n_in,
                              void* d_out, int out_size)
{
    const float* ctl  = (const float*)d_in[1];
    const float* meas = (const float*)d_in[2];
    const float* x0   = (const float*)d_in[3];
    const float* P0   = (const float*)d_in[4];
    const float* Q    = (const float*)d_in[5];
    const float* R    = (const float*)d_in[6];
    const float* dW0  = (const float*)d_in[7];  const float* db0 = (const float*)d_in[8];
    const float* dW1  = (const float*)d_in[9];  const float* db1 = (const float*)d_in[10];
    const float* dW2  = (const float*)d_in[11]; const float* db2 = (const float*)d_in[12];
    const float* dW3  = (const float*)d_in[13]; const float* db3 = (const float*)d_in[14];
    const float* mW0  = (const float*)d_in[15]; const float* mb0 = (const float*)d_in[16];
    const float* mW1  = (const float*)d_in[17]; const float* mb1 = (const float*)d_in[18];
    const float* mW2  = (const float*)d_in[19]; const float* mb2 = (const float*)d_in[20];

    float* out   = (float*)d_out;
    float* o_est = out;                        // [B,T,12]
    float* o_zp  = out + (long)BB*TT*12;       // [B,T,9]
    float* o_cov = out + (long)BB*TT*(12+9);   // [B,T,12,12]

    int smem = (int)sizeof(Smem);
    cudaFuncSetAttribute(ekf_kernel, cudaFuncAttributeMaxDynamicSharedMemorySize, smem);
    ekf_kernel<<<BB, NT, smem>>>(ctl, meas, x0, P0, Q, R,
        dW0,db0,dW1,db1,dW2,db2,dW3,db3,
        mW0,mb0,mW1,mb1,mW2,mb2,
        o_est, o_zp, o_cov);
}